// round 2
// baseline (speedup 1.0000x reference)
#include <cuda_runtime.h>
#include <math.h>

#define NB 2
#define CC 256
#define RCQ 32
#define HH 64
#define WW 64
#define HWP 4096   // H*W
#define C2 512     // 2*C

// ---------------- scratch (device globals; no allocation allowed) ----------------
__device__ float g_rq[NB * RCQ * HWP];
__device__ float g_rk[NB * RCQ * HWP];
__device__ float g_dq[NB * RCQ * HWP];
__device__ float g_dk[NB * RCQ * HWP];
__device__ float g_rv[NB * CC * HWP];
__device__ float g_dv[NB * CC * HWP];
__device__ float g_br[NB * CC * HWP];
__device__ float g_bd[NB * CC * HWP];
__device__ float g_S[(size_t)NB * HWP * HWP];   // 134 MB, reused for both attentions
__device__ float g_invZ[NB * HWP];
__device__ float g_gate[NB * CC * HWP];
__device__ float g_f[NB * C2 * HWP];
__device__ float g_y1[NB * C2 * HWP];
__device__ float g_y2[NB * C2 * HWP];

// ---------------- generic tiled fp32 GEMM: C[M,N] = A[M,K] @ B[K,N] (+bias,+res,*invZ) ----
// A row-major with leading dim lda; B row-major ldb; C row-major ldc=N.
// SCALEA: A[m,k] is multiplied by invZ[k] on load (per-batch invZ, stride K).
// RES: adds res[m*N+n] (per-batch stride sC). ACCUM: C += result. ACT: 0 none, 1 relu.
template <bool ACCUM, int ACT, bool SCALEA, bool RES, bool BIAS>
__global__ void __launch_bounds__(256) gemm_k(
    const float* __restrict__ A, int lda, size_t sA,
    const float* __restrict__ B, int ldb, size_t sB,
    float* __restrict__ C, size_t sC,
    const float* __restrict__ bias,
    const float* __restrict__ res,
    const float* __restrict__ invZ,
    int M, int N, int K)
{
    const int BM = 128, BN = 128, BK = 8, TM = 8, TN = 8;
    int bz = blockIdx.z;
    A += (size_t)bz * sA;
    B += (size_t)bz * sB;
    C += (size_t)bz * sC;
    const float* resp = RES ? res + (size_t)bz * sC : nullptr;
    const float* izp  = SCALEA ? invZ + (size_t)bz * (size_t)K : nullptr;

    __shared__ float As[BK][BM];
    __shared__ float Bs[BK][BN];

    int tid = threadIdx.x;
    int tx = tid % 16, ty = tid / 16;
    int m0 = blockIdx.y * BM, n0 = blockIdx.x * BN;

    // A tile loads: 128x8, 4 contiguous k per thread
    int arow = tid >> 1;
    int acol = (tid & 1) * 4;
    // B tile loads: 8x128, 4 contiguous n per thread
    int brow = tid >> 5;
    int bcol = (tid & 31) * 4;

    float acc[TM][TN];
#pragma unroll
    for (int i = 0; i < TM; i++)
#pragma unroll
        for (int j = 0; j < TN; j++) acc[i][j] = 0.f;

    for (int k0 = 0; k0 < K; k0 += BK) {
#pragma unroll
        for (int i = 0; i < 4; i++) {
            int m = m0 + arow;
            int k = k0 + acol + i;
            float v = 0.f;
            if (m < M && k < K) {
                v = A[(size_t)m * lda + k];
                if (SCALEA) v *= izp[k];
            }
            As[acol + i][arow] = v;
        }
#pragma unroll
        for (int i = 0; i < 4; i++) {
            int k = k0 + brow;
            int n = n0 + bcol + i;
            float v = 0.f;
            if (k < K && n < N) v = B[(size_t)k * ldb + n];
            Bs[brow][bcol + i] = v;
        }
        __syncthreads();
#pragma unroll
        for (int kk = 0; kk < BK; kk++) {
            float a[TM], b[TN];
#pragma unroll
            for (int i = 0; i < TM; i++) a[i] = As[kk][ty * TM + i];
#pragma unroll
            for (int j = 0; j < TN; j++) b[j] = Bs[kk][tx * TN + j];
#pragma unroll
            for (int i = 0; i < TM; i++)
#pragma unroll
                for (int j = 0; j < TN; j++) acc[i][j] += a[i] * b[j];
        }
        __syncthreads();
    }

#pragma unroll
    for (int i = 0; i < TM; i++) {
        int m = m0 + ty * TM + i;
        if (m >= M) continue;
        float bv = BIAS ? bias[m] : 0.f;
#pragma unroll
        for (int j = 0; j < TN; j++) {
            int n = n0 + tx * TN + j;
            if (n >= N) continue;
            size_t idx = (size_t)m * N + n;
            float v = acc[i][j] + bv;
            if (RES) v += resp[idx];
            if (ACCUM) v += C[idx];
            if (ACT == 1) v = fmaxf(v, 0.f);
            C[idx] = v;
        }
    }
}

// ---------------- attention logits + exp: S[i,j] = exp(sum_r Q[r,i]*K[r,j]) ----------------
__global__ void __launch_bounds__(256) attn_exp_k(
    const float* __restrict__ Q, const float* __restrict__ Km, float* __restrict__ S)
{
    int bz = blockIdx.z;
    Q  += (size_t)bz * RCQ * HWP;
    Km += (size_t)bz * RCQ * HWP;
    S  += (size_t)bz * HWP * (size_t)HWP;

    __shared__ float Qs[RCQ][64];
    __shared__ float Ks[RCQ][64];

    int i0 = blockIdx.y * 64, j0 = blockIdx.x * 64;
    int tid = threadIdx.x;
    for (int t = tid; t < RCQ * 64; t += 256) {
        int r = t >> 6, c = t & 63;
        Qs[r][c] = Q[(size_t)r * HWP + i0 + c];
        Ks[r][c] = Km[(size_t)r * HWP + j0 + c];
    }
    __syncthreads();

    int tx = tid % 16, ty = tid / 16;
    float acc[4][4];
#pragma unroll
    for (int i = 0; i < 4; i++)
#pragma unroll
        for (int j = 0; j < 4; j++) acc[i][j] = 0.f;

#pragma unroll
    for (int r = 0; r < RCQ; r++) {
        float q[4], k[4];
#pragma unroll
        for (int i = 0; i < 4; i++) q[i] = Qs[r][ty * 4 + i];
#pragma unroll
        for (int j = 0; j < 4; j++) k[j] = Ks[r][tx * 4 + j];
#pragma unroll
        for (int i = 0; i < 4; i++)
#pragma unroll
            for (int j = 0; j < 4; j++) acc[i][j] += q[i] * k[j];
    }
#pragma unroll
    for (int i = 0; i < 4; i++) {
        size_t row = (size_t)(i0 + ty * 4 + i) * HWP + j0 + tx * 4;
#pragma unroll
        for (int j = 0; j < 4; j++) S[row + j] = __expf(acc[i][j]);
    }
}

// ---------------- row sum -> 1/Z ----------------
__global__ void __launch_bounds__(256) rowsum_inv_k(
    const float* __restrict__ S, float* __restrict__ invZ)
{
    int i = blockIdx.x;
    int bz = blockIdx.y;
    const float* row = S + (size_t)bz * HWP * HWP + (size_t)i * HWP;
    float s = 0.f;
    for (int j = threadIdx.x; j < HWP; j += 256) s += row[j];
    __shared__ float red[256];
    red[threadIdx.x] = s;
    __syncthreads();
    for (int o = 128; o > 0; o >>= 1) {
        if (threadIdx.x < o) red[threadIdx.x] += red[threadIdx.x + o];
        __syncthreads();
    }
    if (threadIdx.x == 0) invZ[bz * HWP + i] = 1.f / red[0];
}

// ---------------- gated combine: f = [br*g + bd*(1-g); br*bd], g = sigmoid(gate_pre) ------
__global__ void __launch_bounds__(256) combine_k(
    const float* __restrict__ br, const float* __restrict__ bd,
    const float* __restrict__ gpre, float* __restrict__ f)
{
    size_t idx = (size_t)blockIdx.x * 256 + threadIdx.x;  // over NB*CC*HWP
    size_t n = idx / ((size_t)CC * HWP);
    size_t r = idx % ((size_t)CC * HWP);
    float a = br[idx], b = bd[idx];
    float g = 1.f / (1.f + __expf(-gpre[idx]));
    size_t base = n * (size_t)C2 * HWP;
    f[base + r] = a * g + b * (1.f - g);
    f[base + (size_t)CC * HWP + r] = a * b;
}

// ---------------- direct 3x3 conv, 512->512, SAME pad, relu+bias fused ----------------
// Block: 64 out channels x one image row (64 px). Each thread: 8 oc x 2 px.
__global__ void __launch_bounds__(256) conv3x3_k(
    const float* __restrict__ in, const float* __restrict__ w,
    const float* __restrict__ bias, float* __restrict__ out)
{
    const int CIN = C2, CK = 8, TO = 64;
    int octile = blockIdx.x;   // 0..7
    int y = blockIdx.y;        // 0..63
    int n = blockIdx.z;
    int tid = threadIdx.x;
    int xp = tid & 31;         // x-pair index
    int ocg = tid >> 5;        // 0..7
    int x0 = xp * 2;
    int oc0 = octile * TO;

    __shared__ float ws[CK][TO][9];
    __shared__ float is[CK][3][66];

    float acc[8][2];
#pragma unroll
    for (int o = 0; o < 8; o++) { acc[o][0] = 0.f; acc[o][1] = 0.f; }

    for (int ci0 = 0; ci0 < CIN; ci0 += CK) {
        for (int t = tid; t < CK * TO * 9; t += 256) {
            int oc = t / (CK * 9);
            int rem = t % (CK * 9);
            int ci = rem / 9, tap = rem % 9;
            ws[ci][oc][tap] = w[((size_t)(oc0 + oc) * CIN + ci0 + ci) * 9 + tap];
        }
        for (int t = tid; t < CK * 3 * 66; t += 256) {
            int ci = t / 198;
            int rem = t % 198;
            int ry = rem / 66;
            int sx = rem % 66;
            int xx = sx - 1;
            int yy = y + ry - 1;
            float v = 0.f;
            if (yy >= 0 && yy < HH && xx >= 0 && xx < WW)
                v = in[(((size_t)n * CIN + ci0 + ci) * HH + yy) * WW + xx];
            is[ci][ry][sx] = v;
        }
        __syncthreads();
#pragma unroll
        for (int ci = 0; ci < CK; ci++) {
            float iv[3][4];
#pragma unroll
            for (int ry = 0; ry < 3; ry++)
#pragma unroll
                for (int dx = 0; dx < 4; dx++) iv[ry][dx] = is[ci][ry][x0 + dx];
#pragma unroll
            for (int o = 0; o < 8; o++) {
                const float* wp = ws[ci][ocg * 8 + o];
#pragma unroll
                for (int ky = 0; ky < 3; ky++)
#pragma unroll
                    for (int kx = 0; kx < 3; kx++) {
                        float wv = wp[ky * 3 + kx];
                        acc[o][0] += wv * iv[ky][kx];
                        acc[o][1] += wv * iv[ky][kx + 1];
                    }
            }
        }
        __syncthreads();
    }
#pragma unroll
    for (int o = 0; o < 8; o++) {
        int oc = oc0 + ocg * 8 + o;
        float b = bias[oc];
        float v0 = fmaxf(acc[o][0] + b, 0.f);
        float v1 = fmaxf(acc[o][1] + b, 0.f);
        size_t base = (((size_t)n * CIN + oc) * HH + y) * WW + x0;
        out[base] = v0;
        out[base + 1] = v1;
    }
}

// ---------------- host launcher ----------------
extern "C" void kernel_launch(void* const* d_in, const int* in_sizes, int n_in,
                              void* d_out, int out_size)
{
    const float* rgb  = (const float*)d_in[0];
    const float* chm  = (const float*)d_in[1];
    const float* rq_w = (const float*)d_in[2];  const float* rq_b = (const float*)d_in[3];
    const float* rk_w = (const float*)d_in[4];  const float* rk_b = (const float*)d_in[5];
    const float* rv_w = (const float*)d_in[6];  const float* rv_b = (const float*)d_in[7];
    const float* dq_w = (const float*)d_in[8];  const float* dq_b = (const float*)d_in[9];
    const float* dk_w = (const float*)d_in[10]; const float* dk_b = (const float*)d_in[11];
    const float* dv_w = (const float*)d_in[12]; const float* dv_b = (const float*)d_in[13];
    const float* gate_w = (const float*)d_in[14]; const float* gate_b = (const float*)d_in[15];
    const float* fus1_w = (const float*)d_in[16]; const float* fus1_b = (const float*)d_in[17];
    const float* fus2_w = (const float*)d_in[18]; const float* fus2_b = (const float*)d_in[19];
    const float* fus3_w = (const float*)d_in[20]; const float* fus3_b = (const float*)d_in[21];
    const float* skip_w = (const float*)d_in[22]; const float* skip_b = (const float*)d_in[23];
    float* out = (float*)d_out;

    float *rq, *rk, *dq, *dk, *rv, *dv, *br, *bd, *S, *invZ, *gate, *f, *y1, *y2;
    cudaGetSymbolAddress((void**)&rq, g_rq);
    cudaGetSymbolAddress((void**)&rk, g_rk);
    cudaGetSymbolAddress((void**)&dq, g_dq);
    cudaGetSymbolAddress((void**)&dk, g_dk);
    cudaGetSymbolAddress((void**)&rv, g_rv);
    cudaGetSymbolAddress((void**)&dv, g_dv);
    cudaGetSymbolAddress((void**)&br, g_br);
    cudaGetSymbolAddress((void**)&bd, g_bd);
    cudaGetSymbolAddress((void**)&S, g_S);
    cudaGetSymbolAddress((void**)&invZ, g_invZ);
    cudaGetSymbolAddress((void**)&gate, g_gate);
    cudaGetSymbolAddress((void**)&f, g_f);
    cudaGetSymbolAddress((void**)&y1, g_y1);
    cudaGetSymbolAddress((void**)&y2, g_y2);

    dim3 blk(256);
    auto grid_mn = [](int M, int N) {
        return dim3((unsigned)((N + 127) / 128), (unsigned)((M + 127) / 128), NB);
    };
    const size_t sX = (size_t)CC * HWP;       // per-batch stride of C-channel tensors
    const size_t sQ = (size_t)RCQ * HWP;      // per-batch stride of rc-channel tensors
    const size_t sS = (size_t)HWP * HWP;      // per-batch stride of attention scratch
    const size_t sF = (size_t)C2 * HWP;       // per-batch stride of 2C-channel tensors

    // --- projections (1x1 convs as GEMMs) ---
    gemm_k<false, 0, false, false, true><<<grid_mn(RCQ, HWP), blk>>>(
        rq_w, CC, 0, rgb, HWP, sX, rq, sQ, rq_b, nullptr, nullptr, RCQ, HWP, CC);
    gemm_k<false, 0, false, false, true><<<grid_mn(RCQ, HWP), blk>>>(
        rk_w, CC, 0, rgb, HWP, sX, rk, sQ, rk_b, nullptr, nullptr, RCQ, HWP, CC);
    gemm_k<false, 0, false, false, true><<<grid_mn(CC, HWP), blk>>>(
        rv_w, CC, 0, rgb, HWP, sX, rv, sX, rv_b, nullptr, nullptr, CC, HWP, CC);
    gemm_k<false, 0, false, false, true><<<grid_mn(RCQ, HWP), blk>>>(
        dq_w, CC, 0, chm, HWP, sX, dq, sQ, dq_b, nullptr, nullptr, RCQ, HWP, CC);
    gemm_k<false, 0, false, false, true><<<grid_mn(RCQ, HWP), blk>>>(
        dk_w, CC, 0, chm, HWP, sX, dk, sQ, dk_b, nullptr, nullptr, RCQ, HWP, CC);
    gemm_k<false, 0, false, false, true><<<grid_mn(CC, HWP), blk>>>(
        dv_w, CC, 0, chm, HWP, sX, dv, sX, dv_b, nullptr, nullptr, CC, HWP, CC);

    // --- attention R: rgb_attn = softmax(dq.dk), br = rv @ attn + rgb ---
    attn_exp_k<<<dim3(64, 64, NB), blk>>>(dq, dk, S);
    rowsum_inv_k<<<dim3(HWP, NB), blk>>>(S, invZ);
    gemm_k<false, 0, true, true, false><<<grid_mn(CC, HWP), blk>>>(
        rv, HWP, sX, S, HWP, sS, br, sX, nullptr, rgb, invZ, CC, HWP, HWP);

    // --- attention D: depth_attn = softmax(rq.rk), bd = dv @ attn + chm ---
    attn_exp_k<<<dim3(64, 64, NB), blk>>>(rq, rk, S);
    rowsum_inv_k<<<dim3(HWP, NB), blk>>>(S, invZ);
    gemm_k<false, 0, true, true, false><<<grid_mn(CC, HWP), blk>>>(
        dv, HWP, sX, S, HWP, sS, bd, sX, nullptr, chm, invZ, CC, HWP, HWP);

    // --- gate pre-activation: gate = Wg[:, :C] @ br + Wg[:, C:] @ bd + bg ---
    gemm_k<false, 0, false, false, true><<<grid_mn(CC, HWP), blk>>>(
        gate_w, C2, 0, br, HWP, sX, gate, sX, gate_b, nullptr, nullptr, CC, HWP, CC);
    gemm_k<true, 0, false, false, false><<<grid_mn(CC, HWP), blk>>>(
        gate_w + CC, C2, 0, bd, HWP, sX, gate, sX, nullptr, nullptr, nullptr, CC, HWP, CC);

    // --- gated fusion -> f = [c_fused; d_fused] ---
    combine_k<<<(unsigned)((size_t)NB * CC * HWP / 256), blk>>>(br, bd, gate, f);

    // --- fus1: y1 = relu(W1 @ f + b1) ---
    gemm_k<false, 1, false, false, true><<<grid_mn(C2, HWP), blk>>>(
        fus1_w, C2, 0, f, HWP, sF, y1, sF, fus1_b, nullptr, nullptr, C2, HWP, C2);

    // --- fus2: y2 = relu(conv3x3(y1) + b2) ---
    conv3x3_k<<<dim3(8, HH, NB), blk>>>(y1, fus2_w, fus2_b, y2);

    // --- head: out = W3 @ y2 + b3 + Wskip @ f + bskip ---
    gemm_k<false, 0, false, false, true><<<grid_mn(CC, HWP), blk>>>(
        fus3_w, C2, 0, y2, HWP, sF, out, sX, fus3_b, nullptr, nullptr, CC, HWP, C2);
    gemm_k<true, 0, false, false, true><<<grid_mn(CC, HWP), blk>>>(
        skip_w, C2, 0, f, HWP, sF, out, sX, skip_b, nullptr, nullptr, CC, HWP, C2);

    (void)in_sizes; (void)n_in; (void)out_size;
}